// round 10
// baseline (speedup 1.0000x reference)
#include <cuda_runtime.h>
#include <cuda_bf16.h>
#include <cstdint>

#define HID   64
#define NFLD  2
#define NHH   32
#define NMF   8
#define NTS   4
#define NLAY  9
#define MAXN  10016

// ---------------- scratch (device globals; no allocation allowed) -----------
__device__ float g_Ptop[MAXN * HID];
__device__ float g_Pbot[MAXN * HID];
__device__ float g_acc [MAXN * HID];
__device__ float g_meshh[MAXN * NHH];
__device__ float g_Fprev[MAXN * NFLD];
__device__ int   g_ctr;
// pre-converted edge weights: [set][layer][n][k] bf16 hi/lo, chunk-swizzled
__device__ __align__(16) __nv_bfloat16 g_WBhi[2][NLAY * HID * HID];
__device__ __align__(16) __nv_bfloat16 g_WBlo[2][NLAY * HID * HID];

// ---------------- helpers -----------------------------------------------------
__device__ __forceinline__ uint32_t s2u(const void* p) {
    uint32_t a;
    asm("{ .reg .u64 t; cvta.to.shared.u64 t, %1; cvt.u32.u64 %0, t; }"
        : "=r"(a) : "l"(p));
    return a;
}
__device__ __forceinline__ void ldsm4(uint32_t* r, uint32_t addr) {
    asm volatile("ldmatrix.sync.aligned.m8n8.x4.shared.b16 {%0,%1,%2,%3}, [%4];"
                 : "=r"(r[0]), "=r"(r[1]), "=r"(r[2]), "=r"(r[3]) : "r"(addr));
}
__device__ __forceinline__ void mma16816(float* c, const uint32_t* a, const uint32_t* b) {
    asm volatile("mma.sync.aligned.m16n8k16.row.col.f32.bf16.bf16.f32 "
                 "{%0,%1,%2,%3}, {%4,%5,%6,%7}, {%8,%9}, {%0,%1,%2,%3};"
                 : "+f"(c[0]), "+f"(c[1]), "+f"(c[2]), "+f"(c[3])
                 : "r"(a[0]), "r"(a[1]), "r"(a[2]), "r"(a[3]), "r"(b[0]), "r"(b[1]));
}
__device__ __forceinline__ uint32_t packbf(float x, float y) {
    __nv_bfloat16 hx = __float2bfloat16(x), hy = __float2bfloat16(y);
    return (uint32_t)__bfloat16_as_ushort(hx) | ((uint32_t)__bfloat16_as_ushort(hy) << 16);
}
#define GBAR(gid) asm volatile("bar.sync %0, %1;" :: "r"((gid) + 1), "r"(128) : "memory")

// ---------------- weight pre-conversion (once per weight set) ----------------
__global__ void prep_wb_kernel(const float* __restrict__ Wh,
                               __nv_bfloat16* __restrict__ hi,
                               __nv_bfloat16* __restrict__ lo)
{
    int idx = blockIdx.x * 256 + threadIdx.x;
    if (idx >= NLAY * HID * HID) return;
    int l = idx >> 12, r = idx & 4095;
    int j = r >> 6, k = r & 63;
    float w = Wh[l * 4096 + k * 64 + j];
    __nv_bfloat16 h = __float2bfloat16(w);
    __nv_bfloat16 lo_ = __float2bfloat16(w - __bfloat162float(h));
    int off = j * 128 + k * 2;
    int sw  = off ^ ((off >> 3) & 0x70);
    hi[l * 4096 + (sw >> 1)] = h;
    lo[l * 4096 + (sw >> 1)] = lo_;
}

// ---------------- per-node projection (mesh descriptor) ----------------------
__global__ void proj_md_kernel(const float* __restrict__ X,
                               const float* __restrict__ W0,
                               float* __restrict__ Ptop, float* __restrict__ Pbot,
                               float* __restrict__ acc, int Nn, int ctr0)
{
    int idx = blockIdx.x * blockDim.x + threadIdx.x;
    if (idx == 0) g_ctr = ctr0;
    if (idx >= Nn * HID) return;
    int n = idx >> 6, j = idx & 63;
    float st = 0.f, sb = 0.f;
#pragma unroll
    for (int k = 0; k < NMF; k++) {
        float x = X[n * NMF + k];
        st = fmaf(x, W0[k * HID + j], st);
        sb = fmaf(x, W0[(NMF + k) * HID + j], sb);
    }
    Ptop[idx] = st;
    Pbot[idx] = sb;
    acc[idx]  = 0.f;
}

// ---------------- fused node encoder + projection (ds) -----------------------
__global__ void encproj_ds_kernel(const float* __restrict__ meshh,
                                  const float* __restrict__ Fprev,
                                  const float* __restrict__ Fb, int t,
                                  const float* __restrict__ encW,
                                  const float* __restrict__ encb,
                                  const float* __restrict__ W0,
                                  float* __restrict__ Ptop, float* __restrict__ Pbot,
                                  float* __restrict__ acc, int Nn, int ctr0)
{
    __shared__ float sh[4][64];
    int tid = threadIdx.x;
    if (blockIdx.x == 0 && tid == 0) g_ctr = ctr0;
    int q = tid >> 6, j = tid & 63;
    int n = blockIdx.x * 4 + q;
    float s = encb[j];
    if (n < Nn) {
#pragma unroll
        for (int k = 0; k < NHH; k++)
            s = fmaf(meshh[n * NHH + k], encW[k * HID + j], s);
        s = fmaf(Fprev[n * NFLD + 0], encW[(NHH + 0) * HID + j], s);
        s = fmaf(Fprev[n * NFLD + 1], encW[(NHH + 1) * HID + j], s);
        s = fmaf(Fb[n * NTS + t],     encW[(NHH + 2) * HID + j], s);
    }
    sh[q][j] = fmaxf(s, 0.f);
    __syncthreads();
    if (n < Nn) {
        float st = 0.f, sb = 0.f;
#pragma unroll 8
        for (int k = 0; k < HID; k++) {
            float x = sh[q][k];
            st = fmaf(x, W0[k * HID + j], st);
            sb = fmaf(x, W0[(HID + k) * HID + j], sb);
        }
        int idx = n * HID + j;
        Ptop[idx] = st;
        Pbot[idx] = sb;
        acc[idx]  = 0.f;
    }
}

// ---------------- HMMA edge MLP + scatter (persistent, grouped) ---------------
// 1 CTA/SM (256 thr), 2 independent groups x 4 warps, named barriers.
// Each group processes 128-edge tiles (dynamic ticket). Warp tile 64e x 32c.
// bf16x3 split: C = Ah@Wh + Al@Wh + Ah@Wl, fp32 HMMA accum.
// All 9 layers' W (hi+lo, 144KB) + biases resident in smem; A single-buffered
// per group (16KB hi + 16KB lo), 2 group-bars per layer.
#define SM_WHI   0
#define SM_WLO   73728
#define SM_BIAS  147456
#define SM_A     149760
#define SM_TOTAL 215296

__global__ void __launch_bounds__(256, 1)
edge_mlp_tc_kernel(const float* __restrict__ Ptop, const float* __restrict__ Pbot,
                   const float* __restrict__ b0,
                   const __nv_bfloat16* __restrict__ WBhi,
                   const __nv_bfloat16* __restrict__ WBlo,
                   const float* __restrict__ Bh,
                   const int* __restrict__ srcp, const int* __restrict__ dstp,
                   float* __restrict__ acc, int E)
{
    extern __shared__ __align__(1024) char sm[];
    __shared__ int s_next[2];

    const int tid  = threadIdx.x, lane = tid & 31;
    const int g    = tid >> 7;          // group 0/1
    const int tg   = tid & 127;         // tid within group
    const int wg   = (tid >> 5) & 3;    // warp within group
    const int eb   = wg & 1;            // edge half (64 edges)
    const int cb   = wg >> 1;           // col half  (32 cols)
    const int ntiles = (E + 127) >> 7;

    // ---- stage ALL layers' weights + biases (whole CTA, once) ----
    for (int i = tid; i < 4608; i += 256) {
        ((uint4*)(sm + SM_WHI))[i] = ((const uint4*)WBhi)[i];
        ((uint4*)(sm + SM_WLO))[i] = ((const uint4*)WBlo)[i];
    }
    for (int i = tid; i < NLAY * HID; i += 256)
        ((float*)(sm + SM_BIAS))[i] = Bh[i];
    __syncthreads();

    char* Ag = sm + SM_A + g * 32768;
    const uint32_t AhiB = s2u(Ag);
    const uint32_t AloB = AhiB + 16384;
    const uint32_t WhiB = s2u(sm + SM_WHI);
    const uint32_t WloB = s2u(sm + SM_WLO);

    // ldmatrix per-thread row components
    const int rA  = lane & 15, khA = lane >> 4;
    const int nB0 = cb * 32 + (lane & 7) + ((lane >> 4) << 3);
    const int khB = (lane >> 3) & 1;

    int tile = blockIdx.x * 2 + g;

    while (tile < ntiles) {
        const int e0 = tile << 7;

        // ---- gather h0 = relu(Ptop[dst]+Pbot[src]+b0) -> Ahi/Alo ----
        for (int u = tg; u < 128 * 8; u += 128) {
            int e = u & 127, oct = u >> 7;
            int ge = e0 + e;
            float v[8];
            if (ge < E) {
                int d = dstp[ge], s = srcp[ge];
                float4 t0 = *(const float4*)(Ptop + d * HID + oct * 8);
                float4 t1 = *(const float4*)(Ptop + d * HID + oct * 8 + 4);
                float4 p0 = *(const float4*)(Pbot + s * HID + oct * 8);
                float4 p1 = *(const float4*)(Pbot + s * HID + oct * 8 + 4);
                float4 c0 = *(const float4*)(b0 + oct * 8);
                float4 c1 = *(const float4*)(b0 + oct * 8 + 4);
                v[0] = fmaxf(t0.x + p0.x + c0.x, 0.f);
                v[1] = fmaxf(t0.y + p0.y + c0.y, 0.f);
                v[2] = fmaxf(t0.z + p0.z + c0.z, 0.f);
                v[3] = fmaxf(t0.w + p0.w + c0.w, 0.f);
                v[4] = fmaxf(t1.x + p1.x + c1.x, 0.f);
                v[5] = fmaxf(t1.y + p1.y + c1.y, 0.f);
                v[6] = fmaxf(t1.z + p1.z + c1.z, 0.f);
                v[7] = fmaxf(t1.w + p1.w + c1.w, 0.f);
            } else {
#pragma unroll
                for (int i = 0; i < 8; i++) v[i] = 0.f;
            }
            uint32_t hw[4], lw[4];
#pragma unroll
            for (int i = 0; i < 4; i++) {
                float a = v[2 * i], b = v[2 * i + 1];
                __nv_bfloat16 ha = __float2bfloat16(a), hb = __float2bfloat16(b);
                hw[i] = (uint32_t)__bfloat16_as_ushort(ha) | ((uint32_t)__bfloat16_as_ushort(hb) << 16);
                lw[i] = packbf(a - __bfloat162float(ha), b - __bfloat162float(hb));
            }
            int sw = (oct ^ (e & 7)) * 16;
            *(uint4*)(Ag + e * 128 + sw)         = make_uint4(hw[0], hw[1], hw[2], hw[3]);
            *(uint4*)(Ag + 16384 + e * 128 + sw) = make_uint4(lw[0], lw[1], lw[2], lw[3]);
        }
        if (tg == 0) s_next[g] = atomicAdd(&g_ctr, 1);
        GBAR(g);   // A ready; ticket published

        for (int l = 0; l < NLAY; l++) {
            const uint32_t WhiL = WhiB + l * 8192;
            const uint32_t WloL = WloB + l * 8192;

            float C[4][4][4];
#pragma unroll
            for (int mt = 0; mt < 4; mt++)
#pragma unroll
                for (int nt = 0; nt < 4; nt++)
#pragma unroll
                    for (int i = 0; i < 4; i++) C[mt][nt][i] = 0.f;

#pragma unroll
            for (int kt = 0; kt < 4; kt++) {
                uint32_t ah[4][4], al[4][4], bh[4][2], bl[4][2];
#pragma unroll
                for (int mt = 0; mt < 4; mt++) {
                    int e = eb * 64 + mt * 16 + rA;
                    uint32_t off = (uint32_t)(e * 128 + ((((kt << 1) + khA) ^ (e & 7)) << 4));
                    ldsm4(ah[mt], AhiB + off);
                    ldsm4(al[mt], AloB + off);
                }
#pragma unroll
                for (int np = 0; np < 2; np++) {
                    int n = nB0 + np * 16;
                    uint32_t off = (uint32_t)(n * 128 + ((((kt << 1) + khB) ^ (n & 7)) << 4));
                    uint32_t t4[4];
                    ldsm4(t4, WhiL + off);
                    bh[np * 2][0] = t4[0]; bh[np * 2][1] = t4[1];
                    bh[np * 2 + 1][0] = t4[2]; bh[np * 2 + 1][1] = t4[3];
                    ldsm4(t4, WloL + off);
                    bl[np * 2][0] = t4[0]; bl[np * 2][1] = t4[1];
                    bl[np * 2 + 1][0] = t4[2]; bl[np * 2 + 1][1] = t4[3];
                }
#pragma unroll
                for (int mt = 0; mt < 4; mt++)
#pragma unroll
                    for (int nt = 0; nt < 4; nt++) {
                        mma16816(C[mt][nt], ah[mt], bh[nt]);
                        mma16816(C[mt][nt], al[mt], bh[nt]);
                        mma16816(C[mt][nt], ah[mt], bl[nt]);
                    }
            }

            GBAR(g);   // all reads of A done

            const float* bsl = (const float*)(sm + SM_BIAS) + l * HID;

            if (l + 1 < NLAY) {
#pragma unroll
                for (int mt = 0; mt < 4; mt++) {
#pragma unroll
                    for (int half = 0; half < 2; half++) {
                        int e = eb * 64 + mt * 16 + (lane >> 2) + half * 8;
#pragma unroll
                        for (int nt = 0; nt < 4; nt++) {
                            int n = cb * 32 + nt * 8 + (lane & 3) * 2;
                            float v0 = fmaxf(C[mt][nt][half * 2 + 0] + bsl[n], 0.f);
                            float v1 = fmaxf(C[mt][nt][half * 2 + 1] + bsl[n + 1], 0.f);
                            __nv_bfloat16 h0 = __float2bfloat16(v0);
                            __nv_bfloat16 h1 = __float2bfloat16(v1);
                            uint32_t hp = (uint32_t)__bfloat16_as_ushort(h0) |
                                          ((uint32_t)__bfloat16_as_ushort(h1) << 16);
                            uint32_t lp = packbf(v0 - __bfloat162float(h0),
                                                 v1 - __bfloat162float(h1));
                            uint32_t off = (uint32_t)(e * 128 +
                                           ((((cb << 2) + nt) ^ (e & 7)) << 4) + ((lane & 3) << 2));
                            *(uint32_t*)(Ag + off)         = hp;
                            *(uint32_t*)(Ag + 16384 + off) = lp;
                        }
                    }
                }
                GBAR(g);   // A(l+1) ready
            } else {
                // last layer: fp32 atomic scatter by src (C regs only)
#pragma unroll
                for (int mt = 0; mt < 4; mt++) {
#pragma unroll
                    for (int half = 0; half < 2; half++) {
                        int e  = eb * 64 + mt * 16 + (lane >> 2) + half * 8;
                        int ge = e0 + e;
                        if (ge < E) {
                            int node = srcp[ge];
                            float* ap = acc + node * HID;
#pragma unroll
                            for (int nt = 0; nt < 4; nt++) {
                                int n = cb * 32 + nt * 8 + (lane & 3) * 2;
                                atomicAdd(ap + n,     C[mt][nt][half * 2 + 0] + bsl[n]);
                                atomicAdd(ap + n + 1, C[mt][nt][half * 2 + 1] + bsl[n + 1]);
                            }
                        }
                    }
                }
            }
        }

        tile = s_next[g];
    }
}

// ---------------- node decoder (mesh descriptor) -----------------------------
__global__ void dec_md_kernel(const float* __restrict__ acc,
                              const float* __restrict__ dw1, const float* __restrict__ db1,
                              const float* __restrict__ dw2, const float* __restrict__ db2,
                              float* __restrict__ meshh, int Nn)
{
    __shared__ float t1[4][64];
    int tid = threadIdx.x;
    int q = tid >> 6, j = tid & 63;
    int n = blockIdx.x * 4 + q;
    float s = db1[j];
    if (n < Nn) {
#pragma unroll 8
        for (int k = 0; k < HID; k++)
            s = fmaf(acc[n * HID + k], dw1[k * HID + j], s);
    }
    t1[q][j] = fmaxf(s, 0.f);
    __syncthreads();
    if (tid < 128) {
        int q2 = tid >> 5, j2 = tid & 31;
        int n2 = blockIdx.x * 4 + q2;
        if (n2 < Nn) {
            float o = db2[j2];
#pragma unroll 8
            for (int k = 0; k < HID; k++)
                o = fmaf(t1[q2][k], dw2[k * NHH + j2], o);
            meshh[n2 * NHH + j2] = o;
        }
    }
}

// ---------------- node decoder (ds) + Euler step + output --------------------
__global__ void dec_ds_kernel(const float* __restrict__ acc,
                              const float* __restrict__ dw1, const float* __restrict__ db1,
                              const float* __restrict__ dw2, const float* __restrict__ db2,
                              const float* __restrict__ Fprev_in,
                              const float* __restrict__ dtp,
                              float* __restrict__ Fprev_out,
                              float* __restrict__ outF, float* __restrict__ outFd,
                              int step, int nsteps, int Nn)
{
    __shared__ float t1[4][64];
    int tid = threadIdx.x;
    int q = tid >> 6, j = tid & 63;
    int n = blockIdx.x * 4 + q;
    float s = db1[j];
    if (n < Nn) {
#pragma unroll 8
        for (int k = 0; k < HID; k++)
            s = fmaf(acc[n * HID + k], dw1[k * HID + j], s);
    }
    t1[q][j] = fmaxf(s, 0.f);
    __syncthreads();
    if (tid < 8) {
        int q2 = tid >> 1, f = tid & 1;
        int n2 = blockIdx.x * 4 + q2;
        if (n2 < Nn) {
            float o = db2[f];
#pragma unroll 8
            for (int k = 0; k < HID; k++)
                o = fmaf(t1[q2][k], dw2[k * NFLD + f], o);
            float fp = Fprev_in[n2 * NFLD + f];
            float fc = fmaf(dtp[0], o, fp);
            outF [(n2 * nsteps + step) * NFLD + f] = fc;
            outFd[(n2 * nsteps + step) * NFLD + f] = o;
            Fprev_out[n2 * NFLD + f] = fc;
        }
    }
}

// ---------------- launch ------------------------------------------------------
extern "C" void kernel_launch(void* const* d_in, const int* in_sizes, int n_in,
                              void* d_out, int out_size)
{
    const float* F_initial     = (const float*)d_in[0];
    const float* mesh_features = (const float*)d_in[1];
    const int*   edge_index    = (const int*)  d_in[2];
    const float* F_boundary    = (const float*)d_in[3];
    const float* dtp           = (const float*)d_in[4];
    const float* md_w0  = (const float*)d_in[5];
    const float* md_b0  = (const float*)d_in[6];
    const float* md_wh  = (const float*)d_in[7];
    const float* md_bh  = (const float*)d_in[8];
    const float* md_dw1 = (const float*)d_in[9];
    const float* md_db1 = (const float*)d_in[10];
    const float* md_dw2 = (const float*)d_in[11];
    const float* md_db2 = (const float*)d_in[12];
    const float* ds_encw = (const float*)d_in[13];
    const float* ds_encb = (const float*)d_in[14];
    const float* ds_w0  = (const float*)d_in[15];
    const float* ds_b0  = (const float*)d_in[16];
    const float* ds_wh  = (const float*)d_in[17];
    const float* ds_bh  = (const float*)d_in[18];
    const float* ds_dw1 = (const float*)d_in[19];
    const float* ds_db1 = (const float*)d_in[20];
    const float* ds_dw2 = (const float*)d_in[21];
    const float* ds_db2 = (const float*)d_in[22];

    int Nn = in_sizes[0] / NFLD;
    int E  = in_sizes[2] / 2;

    float *Ptop, *Pbot, *acc, *meshh, *Fprev;
    __nv_bfloat16 *wbhi, *wblo;
    cudaGetSymbolAddress((void**)&Ptop,  g_Ptop);
    cudaGetSymbolAddress((void**)&Pbot,  g_Pbot);
    cudaGetSymbolAddress((void**)&acc,   g_acc);
    cudaGetSymbolAddress((void**)&meshh, g_meshh);
    cudaGetSymbolAddress((void**)&Fprev, g_Fprev);
    cudaGetSymbolAddress((void**)&wbhi,  g_WBhi);
    cudaGetSymbolAddress((void**)&wblo,  g_WBlo);

    cudaFuncSetAttribute(edge_mlp_tc_kernel,
                         cudaFuncAttributeMaxDynamicSharedMemorySize, SM_TOTAL);

    const int* srcp = edge_index;
    const int* dstp = edge_index + E;

    int nb_node = (Nn * HID + 255) / 256;
    int nb_dec  = (Nn + 3) / 4;
    int nsteps  = NTS - 1;
    int ntiles  = (E + 127) / 128;
    int nb_edge = (ntiles + 1) / 2;
    if (nb_edge > 148) nb_edge = 148;
    int ctr0 = nb_edge * 2;
    int nb_prep = (NLAY * HID * HID + 255) / 256;

    float* outF  = (float*)d_out;
    float* outFd = outF + (size_t)out_size / 2;

    __nv_bfloat16* wbhi_md = wbhi;
    __nv_bfloat16* wblo_md = wblo;
    __nv_bfloat16* wbhi_ds = wbhi + NLAY * HID * HID;
    __nv_bfloat16* wblo_ds = wblo + NLAY * HID * HID;

    // ---- weight pre-conversion (both sets) ----
    prep_wb_kernel<<<nb_prep, 256>>>(md_wh, wbhi_md, wblo_md);
    prep_wb_kernel<<<nb_prep, 256>>>(ds_wh, wbhi_ds, wblo_ds);

    // ---- mesh descriptor pass ----
    proj_md_kernel<<<nb_node, 256>>>(mesh_features, md_w0, Ptop, Pbot, acc, Nn, ctr0);
    edge_mlp_tc_kernel<<<nb_edge, 256, SM_TOTAL>>>(Ptop, Pbot, md_b0,
                                                   wbhi_md, wblo_md, md_bh,
                                                   srcp, dstp, acc, E);
    dec_md_kernel<<<nb_dec, 256>>>(acc, md_dw1, md_db1, md_dw2, md_db2, meshh, Nn);

    // ---- timesteps ----
    for (int t = 1; t < NTS; t++) {
        const float* fprev_in = (t == 1) ? F_initial : (const float*)Fprev;
        encproj_ds_kernel<<<nb_dec, 256>>>(meshh, fprev_in, F_boundary, t,
                                           ds_encw, ds_encb, ds_w0,
                                           Ptop, Pbot, acc, Nn, ctr0);
        edge_mlp_tc_kernel<<<nb_edge, 256, SM_TOTAL>>>(Ptop, Pbot, ds_b0,
                                                       wbhi_ds, wblo_ds, ds_bh,
                                                       srcp, dstp, acc, E);
        dec_ds_kernel<<<nb_dec, 256>>>(acc, ds_dw1, ds_db1, ds_dw2, ds_db2,
                                       fprev_in, dtp, Fprev, outF, outFd,
                                       t - 1, nsteps, Nn);
    }
}

// round 13
// speedup vs baseline: 1.2844x; 1.2844x over previous
#include <cuda_runtime.h>
#include <cuda_bf16.h>
#include <cstdint>

#define HID   64
#define NFLD  2
#define NHH   32
#define NMF   8
#define NTS   4
#define NLAY  9
#define MAXN  10016

// ---------------- scratch (device globals; no allocation allowed) -----------
__device__ float g_Ptop[MAXN * HID];
__device__ float g_Pbot[MAXN * HID];
__device__ float g_acc [MAXN * HID];
__device__ float g_meshh[MAXN * NHH];
__device__ float g_Fprev[MAXN * NFLD];
// pre-converted edge weights: [set][layer][n][k] bf16 hi/lo, chunk-swizzled
__device__ __align__(16) __nv_bfloat16 g_WBhi[2][NLAY * HID * HID];
__device__ __align__(16) __nv_bfloat16 g_WBlo[2][NLAY * HID * HID];

// ---------------- helpers -----------------------------------------------------
__device__ __forceinline__ uint32_t s2u(const void* p) {
    uint32_t a;
    asm("{ .reg .u64 t; cvta.to.shared.u64 t, %1; cvt.u32.u64 %0, t; }"
        : "=r"(a) : "l"(p));
    return a;
}
__device__ __forceinline__ void ldsm4(uint32_t* r, uint32_t addr) {
    asm volatile("ldmatrix.sync.aligned.m8n8.x4.shared.b16 {%0,%1,%2,%3}, [%4];"
                 : "=r"(r[0]), "=r"(r[1]), "=r"(r[2]), "=r"(r[3]) : "r"(addr));
}
__device__ __forceinline__ void stsm4(uint32_t addr, uint32_t r0, uint32_t r1,
                                      uint32_t r2, uint32_t r3) {
    asm volatile("stmatrix.sync.aligned.m8n8.x4.shared.b16 [%0], {%1,%2,%3,%4};"
                 :: "r"(addr), "r"(r0), "r"(r1), "r"(r2), "r"(r3) : "memory");
}
__device__ __forceinline__ void mma16816(float* c, const uint32_t* a, const uint32_t* b) {
    asm volatile("mma.sync.aligned.m16n8k16.row.col.f32.bf16.bf16.f32 "
                 "{%0,%1,%2,%3}, {%4,%5,%6,%7}, {%8,%9}, {%0,%1,%2,%3};"
                 : "+f"(c[0]), "+f"(c[1]), "+f"(c[2]), "+f"(c[3])
                 : "r"(a[0]), "r"(a[1]), "r"(a[2]), "r"(a[3]), "r"(b[0]), "r"(b[1]));
}
// pack 2 floats -> bf16x2 (low = lo, high = hi), round-nearest-even
__device__ __forceinline__ uint32_t cvt2bf(float lo, float hi_) {
    uint32_t r;
    asm("cvt.rn.bf16x2.f32 %0, %1, %2;" : "=r"(r) : "f"(hi_), "f"(lo));
    return r;
}
#define CP_ASYNC16(dst, src) \
    asm volatile("cp.async.ca.shared.global [%0], [%1], 16;" :: "r"(dst), "l"(src) : "memory")
#define CP_COMMIT() asm volatile("cp.async.commit_group;" ::: "memory")
#define CP_WAIT0()  asm volatile("cp.async.wait_group 0;" ::: "memory")

// ---------------- weight pre-conversion (both sets, one launch) --------------
__global__ void prep_wb_kernel(const float* __restrict__ W_md,
                               const float* __restrict__ W_ds,
                               __nv_bfloat16* __restrict__ hi,
                               __nv_bfloat16* __restrict__ lo)
{
    int idx = blockIdx.x * 256 + threadIdx.x;
    if (idx >= 2 * NLAY * HID * HID) return;
    int set = idx >= NLAY * HID * HID;
    int r0  = idx - set * NLAY * HID * HID;
    const float* Wh = set ? W_ds : W_md;
    int l = r0 >> 12, r = r0 & 4095;
    int j = r >> 6, k = r & 63;
    float w = Wh[l * 4096 + k * 64 + j];
    __nv_bfloat16 h = __float2bfloat16(w);
    __nv_bfloat16 lo_ = __float2bfloat16(w - __bfloat162float(h));
    int off = j * 128 + k * 2;
    int sw  = off ^ ((off >> 3) & 0x70);
    hi[set * NLAY * HID * HID + l * 4096 + (sw >> 1)] = h;
    lo[set * NLAY * HID * HID + l * 4096 + (sw >> 1)] = lo_;
}

// ---------------- per-node projection (mesh descriptor) ----------------------
__global__ void proj_md_kernel(const float* __restrict__ X,
                               const float* __restrict__ W0,
                               float* __restrict__ Ptop, float* __restrict__ Pbot,
                               float* __restrict__ acc, int Nn)
{
    int idx = blockIdx.x * blockDim.x + threadIdx.x;
    if (idx >= Nn * HID) return;
    int n = idx >> 6, j = idx & 63;
    float st0 = 0.f, st1 = 0.f, sb0 = 0.f, sb1 = 0.f;
#pragma unroll
    for (int k = 0; k < NMF; k += 2) {
        float x0 = X[n * NMF + k], x1 = X[n * NMF + k + 1];
        st0 = fmaf(x0, W0[k * HID + j], st0);
        st1 = fmaf(x1, W0[(k + 1) * HID + j], st1);
        sb0 = fmaf(x0, W0[(NMF + k) * HID + j], sb0);
        sb1 = fmaf(x1, W0[(NMF + k + 1) * HID + j], sb1);
    }
    Ptop[idx] = st0 + st1;
    Pbot[idx] = sb0 + sb1;
    acc[idx]  = 0.f;
}

// ---------------- fused node encoder + projection (ds) -----------------------
__global__ void encproj_ds_kernel(const float* __restrict__ meshh,
                                  const float* __restrict__ Fprev,
                                  const float* __restrict__ Fb, int t,
                                  const float* __restrict__ encW,
                                  const float* __restrict__ encb,
                                  const float* __restrict__ W0,
                                  float* __restrict__ Ptop, float* __restrict__ Pbot,
                                  float* __restrict__ acc, int Nn)
{
    __shared__ float sh[4][64];
    int tid = threadIdx.x;
    int q = tid >> 6, j = tid & 63;
    int n = blockIdx.x * 4 + q;
    float s0 = encb[j], s1 = 0.f;
    if (n < Nn) {
#pragma unroll
        for (int k = 0; k < NHH; k += 2) {
            s0 = fmaf(meshh[n * NHH + k],     encW[k * HID + j],       s0);
            s1 = fmaf(meshh[n * NHH + k + 1], encW[(k + 1) * HID + j], s1);
        }
        s0 = fmaf(Fprev[n * NFLD + 0], encW[(NHH + 0) * HID + j], s0);
        s1 = fmaf(Fprev[n * NFLD + 1], encW[(NHH + 1) * HID + j], s1);
        s0 = fmaf(Fb[n * NTS + t],     encW[(NHH + 2) * HID + j], s0);
    }
    sh[q][j] = fmaxf(s0 + s1, 0.f);
    __syncthreads();
    if (n < Nn) {
        float st0 = 0.f, st1 = 0.f, sb0 = 0.f, sb1 = 0.f;
#pragma unroll 8
        for (int k = 0; k < HID; k += 2) {
            float x0 = sh[q][k], x1 = sh[q][k + 1];
            st0 = fmaf(x0, W0[k * HID + j], st0);
            st1 = fmaf(x1, W0[(k + 1) * HID + j], st1);
            sb0 = fmaf(x0, W0[(HID + k) * HID + j], sb0);
            sb1 = fmaf(x1, W0[(HID + k + 1) * HID + j], sb1);
        }
        int idx = n * HID + j;
        Ptop[idx] = st0 + st1;
        Pbot[idx] = sb0 + sb1;
        acc[idx]  = 0.f;
    }
}

// ---------------- HMMA edge MLP + scatter (R9 structure) ----------------------
// Tile 128e x 64c, 256 threads (8 warps: 4 edge-blocks x 2 col-blocks).
// bf16x3 split: C = Ah@Wh + Al@Wh + Ah@Wl (fp32 accum), bias pre-loaded in C.
// Epilogue: fmax + cvt.bf16x2 + stmatrix.x4 (hi & lo), zero scattered STS.
// W staged via cp.async double-buffer; one __syncthreads per layer.
#define SM_A0HI  0
#define SM_A0LO  16384
#define SM_A1HI  32768
#define SM_A1LO  49152
#define SM_W0HI  65536
#define SM_W0LO  73728
#define SM_W1HI  81920
#define SM_W1LO  90112
#define SM_BIAS  98304
#define SM_TOTAL (98304 + NLAY * HID * 4)   // 100608

__global__ void __launch_bounds__(256, 2)
edge_mlp_tc_kernel(const float* __restrict__ Ptop, const float* __restrict__ Pbot,
                   const float* __restrict__ b0,
                   const __nv_bfloat16* __restrict__ WBhi,
                   const __nv_bfloat16* __restrict__ WBlo,
                   const float* __restrict__ Bh,
                   const int* __restrict__ srcp, const int* __restrict__ dstp,
                   float* __restrict__ acc, int E)
{
    extern __shared__ __align__(1024) char sm[];
    const int tid = threadIdx.x, lane = tid & 31, wid = tid >> 5;
    const int eb = wid & 3, cb = wid >> 2;
    const int e0 = blockIdx.x * 128;

    // ---- gather h0 = relu(Ptop[dst]+Pbot[src]+b0), split -> A0 hi/lo ----
    for (int u = tid; u < 128 * 8; u += 256) {
        int e = u & 127, oct = u >> 7;
        int ge = e0 + e;
        float v[8];
        if (ge < E) {
            int d = dstp[ge], s = srcp[ge];
            float4 t0 = *(const float4*)(Ptop + d * HID + oct * 8);
            float4 t1 = *(const float4*)(Ptop + d * HID + oct * 8 + 4);
            float4 p0 = *(const float4*)(Pbot + s * HID + oct * 8);
            float4 p1 = *(const float4*)(Pbot + s * HID + oct * 8 + 4);
            float4 c0 = *(const float4*)(b0 + oct * 8);
            float4 c1 = *(const float4*)(b0 + oct * 8 + 4);
            v[0] = fmaxf(t0.x + p0.x + c0.x, 0.f);
            v[1] = fmaxf(t0.y + p0.y + c0.y, 0.f);
            v[2] = fmaxf(t0.z + p0.z + c0.z, 0.f);
            v[3] = fmaxf(t0.w + p0.w + c0.w, 0.f);
            v[4] = fmaxf(t1.x + p1.x + c1.x, 0.f);
            v[5] = fmaxf(t1.y + p1.y + c1.y, 0.f);
            v[6] = fmaxf(t1.z + p1.z + c1.z, 0.f);
            v[7] = fmaxf(t1.w + p1.w + c1.w, 0.f);
        } else {
#pragma unroll
            for (int i = 0; i < 8; i++) v[i] = 0.f;
        }
        uint32_t hw[4], lw[4];
#pragma unroll
        for (int i = 0; i < 4; i++) {
            float a = v[2 * i], b = v[2 * i + 1];
            uint32_t h = cvt2bf(a, b);
            float haf = __uint_as_float(h << 16);
            float hbf = __uint_as_float(h & 0xFFFF0000u);
            hw[i] = h;
            lw[i] = cvt2bf(a - haf, b - hbf);
        }
        int sw = (oct ^ (e & 7)) * 16;
        *(uint4*)(sm + SM_A0HI + e * 128 + sw) = make_uint4(hw[0], hw[1], hw[2], hw[3]);
        *(uint4*)(sm + SM_A0LO + e * 128 + sw) = make_uint4(lw[0], lw[1], lw[2], lw[3]);
    }

    // ---- stage layer-0 weights (cp.async) + all biases ----
    {
        uint32_t wh = s2u(sm + SM_W0HI), wl = s2u(sm + SM_W0LO);
        const char* gh = (const char*)WBhi;
        const char* gl = (const char*)WBlo;
        for (int i = tid; i < 512; i += 256) {
            CP_ASYNC16(wh + i * 16, gh + i * 16);
            CP_ASYNC16(wl + i * 16, gl + i * 16);
        }
        CP_COMMIT();
        for (int i = tid; i < NLAY * HID; i += 256)
            ((float*)(sm + SM_BIAS))[i] = Bh[i];
    }
    CP_WAIT0();
    __syncthreads();

    // per-thread ldmatrix row components
    const int rA  = lane & 15, khA = lane >> 4;
    const int nB0 = cb * 32 + (lane & 7) + ((lane >> 4) << 3);
    const int khB = (lane >> 3) & 1;
    // stmatrix address base: lane l stores row (l&7) of n-chunk (cb*4 + l>>3)
    const int sli = lane & 7, smm = lane >> 3;
    const uint32_t st_base =
        (uint32_t)((eb * 32 + sli) * 128 + (((cb * 4 + smm) ^ sli) << 4));

    uint32_t ArdHi = s2u(sm + SM_A0HI);   // read buffer (hi); lo = +16384
    uint32_t AwrHi = s2u(sm + SM_A1HI);   // write buffer (hi)

    for (int l = 0; l < NLAY; l++) {
        const uint32_t WhiB = s2u(sm + ((l & 1) ? SM_W1HI : SM_W0HI));
        const uint32_t WloB = s2u(sm + ((l & 1) ? SM_W1LO : SM_W0LO));

        // issue cp.async for next layer's weights into the other W buffer
        if (l + 1 < NLAY) {
            uint32_t wh = s2u(sm + ((l & 1) ? SM_W0HI : SM_W1HI));
            uint32_t wl = s2u(sm + ((l & 1) ? SM_W0LO : SM_W1LO));
            const char* gh = (const char*)(WBhi + (l + 1) * 4096);
            const char* gl = (const char*)(WBlo + (l + 1) * 4096);
            for (int i = tid; i < 512; i += 256) {
                CP_ASYNC16(wh + i * 16, gh + i * 16);
                CP_ASYNC16(wl + i * 16, gl + i * 16);
            }
            CP_COMMIT();
        }

        // ---- C init from bias ----
        const float* bsl = (const float*)(sm + SM_BIAS) + l * HID;
        float C[2][4][4];
#pragma unroll
        for (int nt = 0; nt < 4; nt++) {
            float2 bb = *(const float2*)(bsl + cb * 32 + nt * 8 + (lane & 3) * 2);
#pragma unroll
            for (int mt = 0; mt < 2; mt++) {
                C[mt][nt][0] = bb.x; C[mt][nt][1] = bb.y;
                C[mt][nt][2] = bb.x; C[mt][nt][3] = bb.y;
            }
        }

#pragma unroll
        for (int kt = 0; kt < 4; kt++) {
            uint32_t ah[2][4], al[2][4], bh[4][2], bl[4][2];
#pragma unroll
            for (int mt = 0; mt < 2; mt++) {
                int e = eb * 32 + rA + mt * 16;
                uint32_t off = (uint32_t)(e * 128 + ((((kt << 1) + khA) ^ (e & 7)) << 4));
                ldsm4(ah[mt], ArdHi + off);
                ldsm4(al[mt], ArdHi + 16384 + off);
            }
#pragma unroll
            for (int np = 0; np < 2; np++) {
                int n = nB0 + np * 16;
                uint32_t off = (uint32_t)(n * 128 + ((((kt << 1) + khB) ^ (n & 7)) << 4));
                uint32_t t4[4];
                ldsm4(t4, WhiB + off);
                bh[np * 2][0] = t4[0]; bh[np * 2][1] = t4[1];
                bh[np * 2 + 1][0] = t4[2]; bh[np * 2 + 1][1] = t4[3];
                ldsm4(t4, WloB + off);
                bl[np * 2][0] = t4[0]; bl[np * 2][1] = t4[1];
                bl[np * 2 + 1][0] = t4[2]; bl[np * 2 + 1][1] = t4[3];
            }
#pragma unroll
            for (int mt = 0; mt < 2; mt++)
#pragma unroll
                for (int nt = 0; nt < 4; nt++) {
                    mma16816(C[mt][nt], ah[mt], bh[nt]);
                    mma16816(C[mt][nt], al[mt], bh[nt]);
                    mma16816(C[mt][nt], ah[mt], bl[nt]);
                }
        }

        if (l + 1 < NLAY) {
            // ---- epilogue: relu + re-split + stmatrix into write buffer ----
#pragma unroll
            for (int mt = 0; mt < 2; mt++) {
#pragma unroll
                for (int half = 0; half < 2; half++) {
                    uint32_t hw[4], lw[4];
#pragma unroll
                    for (int nt = 0; nt < 4; nt++) {
                        float v0 = fmaxf(C[mt][nt][half * 2 + 0], 0.f);
                        float v1 = fmaxf(C[mt][nt][half * 2 + 1], 0.f);
                        uint32_t h = cvt2bf(v0, v1);
                        float h0f = __uint_as_float(h << 16);
                        float h1f = __uint_as_float(h & 0xFFFF0000u);
                        hw[nt] = h;
                        lw[nt] = cvt2bf(v0 - h0f, v1 - h1f);
                    }
                    uint32_t ad = AwrHi + st_base + (uint32_t)(mt * 2048 + half * 1024);
                    stsm4(ad,         hw[0], hw[1], hw[2], hw[3]);
                    stsm4(ad + 16384, lw[0], lw[1], lw[2], lw[3]);
                }
            }
            CP_WAIT0();
            __syncthreads();
            uint32_t t = ArdHi; ArdHi = AwrHi; AwrHi = t;
        } else {
            // ---- last layer: fp32 atomic scatter by src (bias already in C) ----
#pragma unroll
            for (int mt = 0; mt < 2; mt++) {
#pragma unroll
                for (int half = 0; half < 2; half++) {
                    int e  = eb * 32 + mt * 16 + (lane >> 2) + half * 8;
                    int ge = e0 + e;
                    if (ge < E) {
                        int node = srcp[ge];
                        float* ap = acc + node * HID;
#pragma unroll
                        for (int nt = 0; nt < 4; nt++) {
                            int n = cb * 32 + nt * 8 + (lane & 3) * 2;
                            atomicAdd(ap + n,     C[mt][nt][half * 2 + 0]);
                            atomicAdd(ap + n + 1, C[mt][nt][half * 2 + 1]);
                        }
                    }
                }
            }
        }
    }
}

// ---------------- node decoder (mesh descriptor) -----------------------------
__global__ void dec_md_kernel(const float* __restrict__ acc,
                              const float* __restrict__ dw1, const float* __restrict__ db1,
                              const float* __restrict__ dw2, const float* __restrict__ db2,
                              float* __restrict__ meshh, int Nn)
{
    __shared__ float t1[4][64];
    int tid = threadIdx.x;
    int q = tid >> 6, j = tid & 63;
    int n = blockIdx.x * 4 + q;
    float s0 = db1[j], s1 = 0.f;
    if (n < Nn) {
#pragma unroll 8
        for (int k = 0; k < HID; k += 2) {
            s0 = fmaf(acc[n * HID + k],     dw1[k * HID + j],       s0);
            s1 = fmaf(acc[n * HID + k + 1], dw1[(k + 1) * HID + j], s1);
        }
    }
    t1[q][j] = fmaxf(s0 + s1, 0.f);
    __syncthreads();
    if (tid < 128) {
        int q2 = tid >> 5, j2 = tid & 31;
        int n2 = blockIdx.x * 4 + q2;
        if (n2 < Nn) {
            float o0 = db2[j2], o1 = 0.f;
#pragma unroll 8
            for (int k = 0; k < HID; k += 2) {
                o0 = fmaf(t1[q2][k],     dw2[k * NHH + j2],       o0);
                o1 = fmaf(t1[q2][k + 1], dw2[(k + 1) * NHH + j2], o1);
            }
            meshh[n2 * NHH + j2] = o0 + o1;
        }
    }
}

// ---------------- node decoder (ds) + Euler step + output --------------------
__global__ void dec_ds_kernel(const float* __restrict__ acc,
                              const float* __restrict__ dw1, const float* __restrict__ db1,
                              const float* __restrict__ dw2, const float* __restrict__ db2,
                              const float* __restrict__ Fprev_in,
                              const float* __restrict__ dtp,
                              float* __restrict__ Fprev_out,
                              float* __restrict__ outF, float* __restrict__ outFd,
                              int step, int nsteps, int Nn)
{
    __shared__ float t1[4][64];
    int tid = threadIdx.x;
    int q = tid >> 6, j = tid & 63;
    int n = blockIdx.x * 4 + q;
    float s0 = db1[j], s1 = 0.f;
    if (n < Nn) {
#pragma unroll 8
        for (int k = 0; k < HID; k += 2) {
            s0 = fmaf(acc[n * HID + k],     dw1[k * HID + j],       s0);
            s1 = fmaf(acc[n * HID + k + 1], dw1[(k + 1) * HID + j], s1);
        }
    }
    t1[q][j] = fmaxf(s0 + s1, 0.f);
    __syncthreads();
    if (tid < 8) {
        int q2 = tid >> 1, f = tid & 1;
        int n2 = blockIdx.x * 4 + q2;
        if (n2 < Nn) {
            float o0 = db2[f], o1 = 0.f;
#pragma unroll 8
            for (int k = 0; k < HID; k += 2) {
                o0 = fmaf(t1[q2][k],     dw2[k * NFLD + f],       o0);
                o1 = fmaf(t1[q2][k + 1], dw2[(k + 1) * NFLD + f], o1);
            }
            float o  = o0 + o1;
            float fp = Fprev_in[n2 * NFLD + f];
            float fc = fmaf(dtp[0], o, fp);
            outF [(n2 * nsteps + step) * NFLD + f] = fc;
            outFd[(n2 * nsteps + step) * NFLD + f] = o;
            Fprev_out[n2 * NFLD + f] = fc;
        }
    }
}

// ---------------- launch ------------------------------------------------------
extern "C" void kernel_launch(void* const* d_in, const int* in_sizes, int n_in,
                              void* d_out, int out_size)
{
    const float* F_initial     = (const float*)d_in[0];
    const float* mesh_features = (const float*)d_in[1];
    const int*   edge_index    = (const int*)  d_in[2];
    const float* F_boundary    = (const float*)d_in[3];
    const float* dtp           = (const float*)d_in[4];
    const float* md_w0  = (const float*)d_in[5];
    const float* md_b0  = (const float*)d_in[6];
    const float* md_wh  = (const float*)d_in[7];
    const float* md_bh  = (const float*)d_in[8];
    const float* md_dw1 = (const float*)d_in[9];
    const float* md_db1 = (const float*)d_in[10];
    const float* md_dw2 = (const float*)d_in[11];
    const float* md_db2 = (const float*)d_in[12];
    const float* ds_encw = (const float*)d_in[13];
    const float* ds_encb = (const float*)d_in[14];
    const float* ds_w0  = (const float*)d_in[15];
    const float* ds_b0  = (const float*)d_in[16];
    const float* ds_wh  = (const float*)d_in[17];
    const float* ds_bh  = (const float*)d_in[18];
    const float* ds_dw1 = (const float*)d_in[19];
    const float* ds_db1 = (const float*)d_in[20];
    const float* ds_dw2 = (const float*)d_in[21];
    const float* ds_db2 = (const float*)d_in[22];

    int Nn = in_sizes[0] / NFLD;
    int E  = in_sizes[2] / 2;

    float *Ptop, *Pbot, *acc, *meshh, *Fprev;
    __nv_bfloat16 *wbhi, *wblo;
    cudaGetSymbolAddress((void**)&Ptop,  g_Ptop);
    cudaGetSymbolAddress((void**)&Pbot,  g_Pbot);
    cudaGetSymbolAddress((void**)&acc,   g_acc);
    cudaGetSymbolAddress((void**)&meshh, g_meshh);
    cudaGetSymbolAddress((void**)&Fprev, g_Fprev);
    cudaGetSymbolAddress((void**)&wbhi,  g_WBhi);
    cudaGetSymbolAddress((void**)&wblo,  g_WBlo);

    cudaFuncSetAttribute(edge_mlp_tc_kernel,
                         cudaFuncAttributeMaxDynamicSharedMemorySize, SM_TOTAL);

    const int* srcp = edge_index;
    const int* dstp = edge_index + E;

    int nb_node = (Nn * HID + 255) / 256;
    int nb_dec  = (Nn + 3) / 4;
    int nsteps  = NTS - 1;
    int nb_edge = (E + 127) / 128;
    int nb_prep = (2 * NLAY * HID * HID + 255) / 256;

    float* outF  = (float*)d_out;
    float* outFd = outF + (size_t)out_size / 2;

    __nv_bfloat16* wbhi_md = wbhi;
    __nv_bfloat16* wblo_md = wblo;
    __nv_bfloat16* wbhi_ds = wbhi + NLAY * HID * HID;
    __nv_bfloat16* wblo_ds = wblo + NLAY * HID * HID;

    // ---- weight pre-conversion (both sets, one launch) ----
    prep_wb_kernel<<<nb_prep, 256>>>(md_wh, ds_wh, wbhi, wblo);

    // ---- mesh descriptor pass ----
    proj_md_kernel<<<nb_node, 256>>>(mesh_features, md_w0, Ptop, Pbot, acc, Nn);
    edge_mlp_tc_kernel<<<nb_edge, 256, SM_TOTAL>>>(Ptop, Pbot, md_b0,
                                                   wbhi_md, wblo_md, md_bh,
                                                   srcp, dstp, acc, E);
    dec_md_kernel<<<nb_dec, 256>>>(acc, md_dw1, md_db1, md_dw2, md_db2, meshh, Nn);

    // ---- timesteps ----
    for (int t = 1; t < NTS; t++) {
        const float* fprev_in = (t == 1) ? F_initial : (const float*)Fprev;
        encproj_ds_kernel<<<nb_dec, 256>>>(meshh, fprev_in, F_boundary, t,
                                           ds_encw, ds_encb, ds_w0,
                                           Ptop, Pbot, acc, Nn);
        edge_mlp_tc_kernel<<<nb_edge, 256, SM_TOTAL>>>(Ptop, Pbot, ds_b0,
                                                       wbhi_ds, wblo_ds, ds_bh,
                                                       srcp, dstp, acc, E);
        dec_ds_kernel<<<nb_dec, 256>>>(acc, ds_dw1, ds_db1, ds_dw2, ds_db2,
                                       fprev_in, dtp, Fprev, outF, outFd,
                                       t - 1, nsteps, Nn);
    }
}